// round 12
// baseline (speedup 1.0000x reference)
#include <cuda_runtime.h>
#include <cuda_fp16.h>

typedef unsigned int u32;

#define SEQ   256
#define LAB   128
#define BATCH 8192
#define ROWS  32               // per CTA: 2 streams x 16 rows
#define NBLK  (BATCH / ROWS)   // 256
#define NTHR  256
#define KP    88               // k-stride in fp16
#define RB    176              // row bytes
#define KC    5                // K=80: 64 h + 8 x + 1 bias + pad
#define ASEG  2816             // one 16x88 fp16 tile

// ---- SMEM byte offsets ----
// A: 8 segs [s][b][hi|lo], seg = ((s*2+b)*2+hl)*ASEG
#define SA    0
#define SB    22528            // B scratch; B_lo stays resident
#define SWOUT 67584            // [64][8] f32
#define SBOUT 69632            // [8] f32
#define STOT  69696

static __device__ __forceinline__ u32 sptr(const void* p) {
    return (u32)__cvta_generic_to_shared(p);
}
static __device__ __forceinline__ void ldm4(u32* r, u32 a) {
    asm volatile("ldmatrix.sync.aligned.m8n8.x4.shared.b16 {%0,%1,%2,%3},[%4];"
        : "=r"(r[0]), "=r"(r[1]), "=r"(r[2]), "=r"(r[3]) : "r"(a));
}
static __device__ __forceinline__ void ldm2(u32* r, u32 a) {
    asm volatile("ldmatrix.sync.aligned.m8n8.x2.shared.b16 {%0,%1},[%2];"
        : "=r"(r[0]), "=r"(r[1]) : "r"(a));
}
static __device__ __forceinline__ void mmaop(float* d, const u32* a, const u32* b) {
    asm volatile("mma.sync.aligned.m16n8k16.row.col.f32.f16.f16.f32 "
        "{%0,%1,%2,%3},{%4,%5,%6,%7},{%8,%9},{%0,%1,%2,%3};"
        : "+f"(d[0]), "+f"(d[1]), "+f"(d[2]), "+f"(d[3])
        : "r"(a[0]), "r"(a[1]), "r"(a[2]), "r"(a[3]), "r"(b[0]), "r"(b[1]));
}
static __device__ __forceinline__ float tanha(float x) {
    float y; asm("tanh.approx.f32 %0,%1;" : "=f"(y) : "f"(x)); return y;
}
static __device__ __forceinline__ float sigt(float x) { return fmaf(0.5f, tanha(0.5f * x), 0.5f); }

// B[n][k]: r 0-63, z 64-127, ni 128-191, nh 192-255.
// fold=0: k<64 Whh (ni zero), k64-71 Wih, k72 bias.
// fold=1: k<64 Whh + Wih@Wout (ni: Wih@Wout), k64-71 zero, k72 bias + Wih@bout.
static __device__ void build_B(half* Bs,
                               const float* __restrict__ Wih, const float* __restrict__ Whh,
                               const float* __restrict__ bih, const float* __restrict__ bhh,
                               const float* __restrict__ Wout, const float* __restrict__ bout,
                               int fold, int term, int tid) {
    for (int i = tid; i < 256 * KP; i += NTHR) {
        int n = i / KP, k = i % KP;
        float v = 0.0f;
        if (k < 64) {
            if (n < 128) v = Whh[n * 64 + k];
            else if (n >= 192) v = Whh[(n - 64) * 64 + k];
            if (fold && n < 192) {
                #pragma unroll
                for (int o = 0; o < 8; o++) v = fmaf(Wih[n * 8 + o], Wout[o * 64 + k], v);
            }
        } else if (k < 72) {
            if (!fold && n < 192) v = Wih[n * 8 + (k - 64)];
        } else if (k == 72) {
            v = (n < 128) ? bih[n] + bhh[n] : (n < 192 ? bih[n] : bhh[n - 64]);
            if (fold && n < 192) {
                #pragma unroll
                for (int o = 0; o < 8; o++) v = fmaf(Wih[n * 8 + o], bout[o], v);
            }
        }
        half h = __float2half_rn(v);
        if (term) h = __float2half_rn(v - __half2float(h));
        Bs[i] = h;
    }
}

static __device__ __forceinline__ void load_frags(u32 fb, int warp, u32 (&Bh)[4][KC][2]) {
    #pragma unroll
    for (int q = 0; q < 4; q++) {
        u32 bq = fb + (u32)((warp + 8 * q) * 8 * RB);
        #pragma unroll
        for (int kc = 0; kc < KC; kc++) ldm2(Bh[q][kc], bq + kc * 32);
    }
}

// One-stream GEMM: D[4 gate-tiles][4]. NIF: ni full-K (folded decoder).
template<bool NIF>
static __device__ __forceinline__ void gemm1(u32 aHi, const u32 (&Bh)[4][KC][2],
                                             const u32 blq[4], float (&D)[4][4]) {
    #pragma unroll
    for (int q = 0; q < 4; q++)
        #pragma unroll
        for (int e = 0; e < 4; e++) D[q][e] = 0.0f;
    #pragma unroll
    for (int kc = 0; kc < KC; kc++) {
        u32 ah[4], al[4];
        ldm4(ah, aHi + kc * 32);
        ldm4(al, aHi + ASEG + kc * 32);
        u32 b0[2], b1[2], b3[2];
        ldm2(b0, blq[0] + kc * 32);
        ldm2(b1, blq[1] + kc * 32);
        ldm2(b3, blq[3] + kc * 32);
        mmaop(D[0], ah, Bh[0][kc]); mmaop(D[0], al, Bh[0][kc]); mmaop(D[0], ah, b0);
        mmaop(D[1], ah, Bh[1][kc]); mmaop(D[1], al, Bh[1][kc]); mmaop(D[1], ah, b1);
        if (NIF || kc == KC - 1) {
            u32 b2[2]; ldm2(b2, blq[2] + kc * 32);
            mmaop(D[2], ah, Bh[2][kc]); mmaop(D[2], al, Bh[2][kc]); mmaop(D[2], ah, b2);
        }
        mmaop(D[3], ah, Bh[3][kc]); mmaop(D[3], al, Bh[3][kc]); mmaop(D[3], ah, b3);
    }
}

// Gates + write h' into target 16-row tile (hi/lo).
static __device__ __forceinline__ void epi1(half* AhiN, half* AloN, int warp, int lane,
                                            const float (&D)[4][4], float (&hold)[4]) {
    const int r0 = lane >> 2;
    const int c0 = warp * 8 + 2 * (lane & 3);
    float h[4];
    #pragma unroll
    for (int j = 0; j < 4; j++) {
        float R = sigt(D[0][j]);
        float Z = sigt(D[1][j]);
        float N = tanha(fmaf(R, D[3][j], D[2][j]));
        h[j] = fmaf(Z, hold[j] - N, N);
        hold[j] = h[j];
    }
    half2 h2a = __floats2half2_rn(h[0], h[1]);
    half2 l2a = __floats2half2_rn(h[0] - __low2float(h2a), h[1] - __high2float(h2a));
    half2 h2b = __floats2half2_rn(h[2], h[3]);
    half2 l2b = __floats2half2_rn(h[2] - __low2float(h2b), h[3] - __high2float(h2b));
    *(half2*)(AhiN + r0 * KP + c0)       = h2a;
    *(half2*)(AloN + r0 * KP + c0)       = l2a;
    *(half2*)(AhiN + (r0 + 8) * KP + c0) = h2b;
    *(half2*)(AloN + (r0 + 8) * KP + c0) = l2b;
}

// Store a staged float4 (x values) into tile: t32 in [0,32): row t32>>1, half (t32&1)*4.
static __device__ __forceinline__ void stage_store(half* Ahi, half* Alo, int t32, float4 v) {
    int r = t32 >> 1, hf = (t32 & 1) * 4;
    half2 a  = __floats2half2_rn(v.x, v.y);
    half2 b  = __floats2half2_rn(v.z, v.w);
    half2 la = __floats2half2_rn(v.x - __low2float(a), v.y - __high2float(a));
    half2 lb = __floats2half2_rn(v.z - __low2float(b), v.w - __high2float(b));
    *(half2*)(Ahi + r * KP + 64 + hf)     = a;
    *(half2*)(Ahi + r * KP + 64 + hf + 2) = b;
    *(half2*)(Alo + r * KP + 64 + hf)     = la;
    *(half2*)(Alo + r * KP + 64 + hf + 2) = lb;
}

// Out-projection for one row of a stream tile (reads hi+lo h from SMEM).
static __device__ __forceinline__ float oproj(const half* Ahi, const half* Alo,
                                              const float* wo, float acc, int r, int oo) {
    const half2* rh = (const half2*)(Ahi + r * KP);
    const half2* rl = (const half2*)(Alo + r * KP);
    #pragma unroll 8
    for (int k2 = 0; k2 < 32; k2++) {
        float2 hq = __half22float2(rh[k2]);
        float2 lq = __half22float2(rl[k2]);
        acc = fmaf(hq.x + lq.x, wo[(2 * k2) * 8 + oo],
              fmaf(hq.y + lq.y, wo[(2 * k2 + 1) * 8 + oo], acc));
    }
    return acc;
}

__global__ __launch_bounds__(NTHR, 2)
void seq2seq_mma_kernel(const float* __restrict__ x,
                        const float* __restrict__ xy,
                        const float* __restrict__ eWih, const float* __restrict__ eWhh,
                        const float* __restrict__ ebih, const float* __restrict__ ebhh,
                        const float* __restrict__ dWih, const float* __restrict__ dWhh,
                        const float* __restrict__ dbih, const float* __restrict__ dbhh,
                        const float* __restrict__ Wout, const float* __restrict__ bout,
                        float* __restrict__ out)
{
    extern __shared__ char smem[];
    half*  Bs = (half*)(smem + SB);
    float* wo = (float*)(smem + SWOUT);
    float* bo = (float*)(smem + SBOUT);

    const int tid  = threadIdx.x;
    const int lane = tid & 31;
    const int warp = tid >> 5;
    const int rowb = blockIdx.x * ROWS;

    // tile pointers: seg(s,b) hi base
    half* Hp[2][2]; half* Lp[2][2];
    #pragma unroll
    for (int s = 0; s < 2; s++)
        #pragma unroll
        for (int b = 0; b < 2; b++) {
            Hp[s][b] = (half*)(smem + SA + ((s * 2 + b) * 2) * ASEG);
            Lp[s][b] = (half*)(smem + SA + ((s * 2 + b) * 2 + 1) * ASEG);
        }

    // ---- init: zero A, wout/bout, bias lanes, stage x[0] both streams ----
    for (int i = tid * 16; i < SB; i += NTHR * 16) *(uint4*)(smem + i) = make_uint4(0, 0, 0, 0);
    for (int i = tid; i < 512; i += NTHR) { int k = i >> 3, o = i & 7; wo[i] = Wout[o * 64 + k]; }
    if (tid < 8) bo[tid] = bout[tid];
    __syncthreads();
    if (tid < 64) {                                   // bias lane k72 = 1.0, all 4 tiles
        int sg = tid >> 4, r = tid & 15;
        Hp[sg >> 1][sg & 1][r * KP + 72] = __float2half(1.0f);
    }
    if (tid < 64) {                                   // x[0]: threads 0-31 stream A, 32-63 B
        int s = tid >> 5, t32 = tid & 31;
        float4 v = *(const float4*)(x + ((size_t)rowb + s * 16 + (t32 >> 1)) * 8 + (t32 & 1) * 4);
        stage_store(Hp[s][0], Lp[s][0], t32, v);
    }
    __syncthreads();

    // ---- encoder B ----
    u32 Bh[4][KC][2];
    const u32 fb = sptr(Bs) + (u32)((lane & 7) * RB + ((lane >> 3) & 1) * 16);
    u32 blq[4];
    #pragma unroll
    for (int q = 0; q < 4; q++) blq[q] = fb + (u32)((warp + 8 * q) * 8 * RB);

    build_B(Bs, eWih, eWhh, ebih, ebhh, Wout, bout, 0, 0, tid);  __syncthreads();
    load_frags(fb, warp, Bh);                                    __syncthreads();
    build_B(Bs, eWih, eWhh, ebih, ebhh, Wout, bout, 0, 1, tid);  __syncthreads();

    // A fragment byte offset within a tile
    u32 aoff;
    { int t8 = lane >> 3, lr = lane & 7;
      aoff = (u32)(((t8 & 1) * 8 + lr) * RB + (t8 >> 1) * 16); }
    u32 aAd[2][2];
    #pragma unroll
    for (int s = 0; s < 2; s++)
        #pragma unroll
        for (int b = 0; b < 2; b++) aAd[s][b] = sptr(Hp[s][b]) + aoff;

    float D_A[4][4], D_B[4][4];
    float holdA[4] = {0, 0, 0, 0}, holdB[4] = {0, 0, 0, 0};
    int cA = 0, cB = 0;

    // =========================== ENCODER (2-stream pipeline) ===========================
    for (int t = 0; t < SEQ; t++) {
        // P1: GEMM_A(t) || epi_B(t-1)+stage xB(t)
        float4 xv; const bool st1 = (t > 0) && (tid < 32);
        if (st1) xv = *(const float4*)(x + ((size_t)t * BATCH + rowb + 16 + (tid >> 1)) * 8 + (tid & 1) * 4);
        gemm1<false>(aAd[0][cA], Bh, blq, D_A);
        if (t > 0) {
            epi1(Hp[1][cB ^ 1], Lp[1][cB ^ 1], warp, lane, D_B, holdB);
            if (st1) stage_store(Hp[1][cB ^ 1], Lp[1][cB ^ 1], tid, xv);
            cB ^= 1;
        }
        __syncthreads();
        // P2: GEMM_B(t) || epi_A(t)+stage xA(t+1)
        float4 xv2; const bool st2 = (t + 1 < SEQ) && (tid < 32);
        if (st2) xv2 = *(const float4*)(x + ((size_t)(t + 1) * BATCH + rowb + (tid >> 1)) * 8 + (tid & 1) * 4);
        gemm1<false>(aAd[1][cB], Bh, blq, D_B);
        epi1(Hp[0][cA ^ 1], Lp[0][cA ^ 1], warp, lane, D_A, holdA);
        if (st2) stage_store(Hp[0][cA ^ 1], Lp[0][cA ^ 1], tid, xv2);
        cA ^= 1;
        __syncthreads();
    }
    epi1(Hp[1][cB ^ 1], Lp[1][cB ^ 1], warp, lane, D_B, holdB);  // drain B
    cB ^= 1;
    __syncthreads();

    // ---- decoder step 0: unfolded weights, x = xy[0] ----
    build_B(Bs, dWih, dWhh, dbih, dbhh, Wout, bout, 0, 0, tid);  __syncthreads();
    load_frags(fb, warp, Bh);                                    __syncthreads();
    build_B(Bs, dWih, dWhh, dbih, dbhh, Wout, bout, 0, 1, tid);
    if (tid < 64) {
        int s = tid >> 5, t32 = tid & 31;
        float4 v = *(const float4*)(xy + ((size_t)rowb + s * 16 + (t32 >> 1)) * 8 + (t32 & 1) * 4);
        stage_store(Hp[s][s ? cB : cA], Lp[s][s ? cB : cA], t32, v);
    }
    __syncthreads();

    gemm1<false>(aAd[0][cA], Bh, blq, D_A);        // P1 (t=0)
    __syncthreads();
    gemm1<false>(aAd[1][cB], Bh, blq, D_B);        // P2 (t=0)
    epi1(Hp[0][cA ^ 1], Lp[0][cA ^ 1], warp, lane, D_A, holdA);
    cA ^= 1;
    __syncthreads();

    // ---- fold Wout into decoder weights (steps >= 1) ----
    build_B(Bs, dWih, dWhh, dbih, dbhh, Wout, bout, 1, 0, tid);  __syncthreads();
    load_frags(fb, warp, Bh);                                    __syncthreads();
    build_B(Bs, dWih, dWhh, dbih, dbhh, Wout, bout, 1, 1, tid);  __syncthreads();

    const int orr = tid >> 3, oo = tid & 7;
    const float bop = bo[oo];

    // =========================== DECODER (folded, out-proj overlapped) =================
    for (int t = 1; t < LAB; t++) {
        // P1: GEMM_A(t) || epi_B(t-1) || outproj_A(t-1)
        gemm1<true>(aAd[0][cA], Bh, blq, D_A);
        epi1(Hp[1][cB ^ 1], Lp[1][cB ^ 1], warp, lane, D_B, holdB);
        cB ^= 1;
        if (tid < 128)
            out[((size_t)(t - 1) * BATCH + rowb + orr) * 8 + oo] =
                oproj(Hp[0][cA], Lp[0][cA], wo, bop, orr, oo);
        __syncthreads();
        // P2: GEMM_B(t) || epi_A(t) || outproj_B(t-1)
        gemm1<true>(aAd[1][cB], Bh, blq, D_B);
        epi1(Hp[0][cA ^ 1], Lp[0][cA ^ 1], warp, lane, D_A, holdA);
        cA ^= 1;
        if (tid < 128)
            out[((size_t)(t - 1) * BATCH + rowb + 16 + orr) * 8 + oo] =
                oproj(Hp[1][cB], Lp[1][cB], wo, bop, orr, oo);
        __syncthreads();
    }
    // drain: epi_B(127), then final projections
    epi1(Hp[1][cB ^ 1], Lp[1][cB ^ 1], warp, lane, D_B, holdB);
    cB ^= 1;
    __syncthreads();
    if (tid < 128) {
        out[((size_t)(LAB - 1) * BATCH + rowb + orr) * 8 + oo] =
            oproj(Hp[0][cA], Lp[0][cA], wo, bop, orr, oo);
        out[((size_t)(LAB - 1) * BATCH + rowb + 16 + orr) * 8 + oo] =
            oproj(Hp[1][cB], Lp[1][cB], wo, bop, orr, oo);
    }
}

extern "C" void kernel_launch(void* const* d_in, const int* in_sizes, int n_in,
                              void* d_out, int out_size) {
    (void)in_sizes; (void)n_in; (void)out_size;
    cudaFuncSetAttribute(seq2seq_mma_kernel,
                         cudaFuncAttributeMaxDynamicSharedMemorySize, STOT);
    seq2seq_mma_kernel<<<NBLK, NTHR, STOT>>>(
        (const float*)d_in[0], (const float*)d_in[1],
        (const float*)d_in[2], (const float*)d_in[3],
        (const float*)d_in[4], (const float*)d_in[5],
        (const float*)d_in[6], (const float*)d_in[7],
        (const float*)d_in[8], (const float*)d_in[9],
        (const float*)d_in[10], (const float*)d_in[11],
        (float*)d_out);
}

// round 13
// speedup vs baseline: 1.1955x; 1.1955x over previous
#include <cuda_runtime.h>
#include <cuda_fp16.h>

typedef unsigned int u32;

#define SEQ   256
#define LAB   128
#define BATCH 8192
#define ROWS  32
#define NBLK  (BATCH / ROWS)   // 256
#define NTHR  256
#define KP    88
#define RB    176
#define KC    5                // K=80: 64 h + 8 x + 1 bias + pad

// ---- SMEM byte offsets ----
// A: [2 buf][hi|lo][32][88] fp16.  buf stride 11264, hi->lo +5632
#define SA    0
#define ABUF  11264
#define ALO   5632
#define SB    22528            // B scratch; B_lo stays resident
#define SWOUT 67584            // [64][8] f32
#define SBOUT 69632            // [8] f32
#define STOT  69696

static __device__ __forceinline__ u32 sptr(const void* p) {
    return (u32)__cvta_generic_to_shared(p);
}
static __device__ __forceinline__ void ldm4(u32* r, u32 a) {
    asm volatile("ldmatrix.sync.aligned.m8n8.x4.shared.b16 {%0,%1,%2,%3},[%4];"
        : "=r"(r[0]), "=r"(r[1]), "=r"(r[2]), "=r"(r[3]) : "r"(a));
}
static __device__ __forceinline__ void ldm2(u32* r, u32 a) {
    asm volatile("ldmatrix.sync.aligned.m8n8.x2.shared.b16 {%0,%1},[%2];"
        : "=r"(r[0]), "=r"(r[1]) : "r"(a));
}
static __device__ __forceinline__ void mmaop(float* d, const u32* a, const u32* b) {
    asm volatile("mma.sync.aligned.m16n8k16.row.col.f32.f16.f16.f32 "
        "{%0,%1,%2,%3},{%4,%5,%6,%7},{%8,%9},{%0,%1,%2,%3};"
        : "+f"(d[0]), "+f"(d[1]), "+f"(d[2]), "+f"(d[3])
        : "r"(a[0]), "r"(a[1]), "r"(a[2]), "r"(a[3]), "r"(b[0]), "r"(b[1]));
}
static __device__ __forceinline__ float tanha(float x) {
    float y; asm("tanh.approx.f32 %0,%1;" : "=f"(y) : "f"(x)); return y;
}
static __device__ __forceinline__ float sigt(float x) { return fmaf(0.5f, tanha(0.5f * x), 0.5f); }

// B[n][k]: r 0-63, z 64-127, ni 128-191, nh 192-255.
// fold=0: k<64 Whh (ni zero), k64-71 Wih, k72 bias.
// fold=1: k<64 Whh + Wih@Wout (ni: Wih@Wout), k64-71 zero, k72 bias + Wih@bout.
static __device__ void build_B(half* Bs,
                               const float* __restrict__ Wih, const float* __restrict__ Whh,
                               const float* __restrict__ bih, const float* __restrict__ bhh,
                               const float* __restrict__ Wout, const float* __restrict__ bout,
                               int fold, int term, int tid) {
    for (int i = tid; i < 256 * KP; i += NTHR) {
        int n = i / KP, k = i % KP;
        float v = 0.0f;
        if (k < 64) {
            if (n < 128) v = Whh[n * 64 + k];
            else if (n >= 192) v = Whh[(n - 64) * 64 + k];
            if (fold && n < 192) {
                #pragma unroll
                for (int o = 0; o < 8; o++) v = fmaf(Wih[n * 8 + o], Wout[o * 64 + k], v);
            }
        } else if (k < 72) {
            if (!fold && n < 192) v = Wih[n * 8 + (k - 64)];
        } else if (k == 72) {
            v = (n < 128) ? bih[n] + bhh[n] : (n < 192 ? bih[n] : bhh[n - 64]);
            if (fold && n < 192) {
                #pragma unroll
                for (int o = 0; o < 8; o++) v = fmaf(Wih[n * 8 + o], bout[o], v);
            }
        }
        half h = __float2half_rn(v);
        if (term) h = __float2half_rn(v - __half2float(h));
        Bs[i] = h;
    }
}

static __device__ __forceinline__ void load_frags(u32 fb, int warp, u32 (&Bh)[4][KC][2]) {
    #pragma unroll
    for (int q = 0; q < 4; q++) {
        u32 bq = fb + (u32)((warp + 8 * q) * 8 * RB);
        #pragma unroll
        for (int kc = 0; kc < KC; kc++) ldm2(Bh[q][kc], bq + kc * 32);
    }
}

// Two m-tile GEMM. NIF: ni full-K (folded decoder); else ni only kc=4.
template<bool NIF>
static __device__ __forceinline__ void gemm_step(u32 aHi0, u32 aHi1, const u32 blq[4],
                                                 const u32 (&Bh)[4][KC][2], float (&D)[2][4][4]) {
    #pragma unroll
    for (int mt = 0; mt < 2; mt++)
        #pragma unroll
        for (int q = 0; q < 4; q++)
            #pragma unroll
            for (int e = 0; e < 4; e++) D[mt][q][e] = 0.0f;
    #pragma unroll
    for (int kc = 0; kc < KC; kc++) {
        u32 ah[2][4], al[2][4];
        ldm4(ah[0], aHi0 + kc * 32);
        ldm4(ah[1], aHi1 + kc * 32);
        ldm4(al[0], aHi0 + ALO + kc * 32);
        ldm4(al[1], aHi1 + ALO + kc * 32);
        u32 b0[2], b1[2], b3[2];
        ldm2(b0, blq[0] + kc * 32);
        ldm2(b1, blq[1] + kc * 32);
        ldm2(b3, blq[3] + kc * 32);
        #pragma unroll
        for (int mt = 0; mt < 2; mt++) {
            mmaop(D[mt][0], ah[mt], Bh[0][kc]); mmaop(D[mt][0], al[mt], Bh[0][kc]); mmaop(D[mt][0], ah[mt], b0);
            mmaop(D[mt][1], ah[mt], Bh[1][kc]); mmaop(D[mt][1], al[mt], Bh[1][kc]); mmaop(D[mt][1], ah[mt], b1);
            mmaop(D[mt][3], ah[mt], Bh[3][kc]); mmaop(D[mt][3], al[mt], Bh[3][kc]); mmaop(D[mt][3], ah[mt], b3);
        }
        if (NIF || kc == KC - 1) {
            u32 b2[2]; ldm2(b2, blq[2] + kc * 32);
            #pragma unroll
            for (int mt = 0; mt < 2; mt++) {
                mmaop(D[mt][2], ah[mt], Bh[2][kc]); mmaop(D[mt][2], al[mt], Bh[2][kc]); mmaop(D[mt][2], ah[mt], b2);
            }
        }
    }
}

// Gates in regs; write h' (hi/lo) into next A buffer.
static __device__ __forceinline__ void epi(half* AhiN, half* AloN, int warp, int lane,
                                           float (&D)[2][4][4], float (&hold)[2][4]) {
    const int r0 = lane >> 2;
    const int c0 = warp * 8 + 2 * (lane & 3);
    #pragma unroll
    for (int mt = 0; mt < 2; mt++) {
        float h[4];
        #pragma unroll
        for (int j = 0; j < 4; j++) {
            float R = sigt(D[mt][0][j]);
            float Z = sigt(D[mt][1][j]);
            float N = tanha(fmaf(R, D[mt][3][j], D[mt][2][j]));
            h[j] = fmaf(Z, hold[mt][j] - N, N);
            hold[mt][j] = h[j];
        }
        int ra = mt * 16 + r0, rb = ra + 8;
        half2 h2a = __floats2half2_rn(h[0], h[1]);
        half2 l2a = __floats2half2_rn(h[0] - __low2float(h2a), h[1] - __high2float(h2a));
        half2 h2b = __floats2half2_rn(h[2], h[3]);
        half2 l2b = __floats2half2_rn(h[2] - __low2float(h2b), h[3] - __high2float(h2b));
        *(half2*)(AhiN + ra * KP + c0) = h2a;
        *(half2*)(AloN + ra * KP + c0) = l2a;
        *(half2*)(AhiN + rb * KP + c0) = h2b;
        *(half2*)(AloN + rb * KP + c0) = l2b;
    }
}

static __device__ __forceinline__ void stage_x(half* Ahi, half* Alo, int row, const float* v) {
    #pragma unroll
    for (int j = 0; j < 4; j++) {
        float a = v[2 * j], b = v[2 * j + 1];
        half2 h2 = __floats2half2_rn(a, b);
        half2 l2 = __floats2half2_rn(a - __low2float(h2), b - __high2float(h2));
        *(half2*)(Ahi + row * KP + 64 + 2 * j) = h2;
        *(half2*)(Alo + row * KP + 64 + 2 * j) = l2;
    }
}

// Out-projection: one scalar out for (row r, output oo), reading h from buffer.
static __device__ __forceinline__ float oproj(const half* Ahi, const half* Alo,
                                              const float* wo, float acc, int r, int oo) {
    const half2* rh = (const half2*)(Ahi + r * KP);
    const half2* rl = (const half2*)(Alo + r * KP);
    #pragma unroll 8
    for (int k2 = 0; k2 < 32; k2++) {
        float2 hq = __half22float2(rh[k2]);
        float2 lq = __half22float2(rl[k2]);
        acc = fmaf(hq.x + lq.x, wo[(2 * k2) * 8 + oo],
              fmaf(hq.y + lq.y, wo[(2 * k2 + 1) * 8 + oo], acc));
    }
    return acc;
}

__global__ __launch_bounds__(NTHR, 2)
void seq2seq_mma_kernel(const float* __restrict__ x,
                        const float* __restrict__ xy,
                        const float* __restrict__ eWih, const float* __restrict__ eWhh,
                        const float* __restrict__ ebih, const float* __restrict__ ebhh,
                        const float* __restrict__ dWih, const float* __restrict__ dWhh,
                        const float* __restrict__ dbih, const float* __restrict__ dbhh,
                        const float* __restrict__ Wout, const float* __restrict__ bout,
                        float* __restrict__ out)
{
    extern __shared__ char smem[];
    half*  Bs = (half*)(smem + SB);
    float* wo = (float*)(smem + SWOUT);
    float* bo = (float*)(smem + SBOUT);

    const int tid  = threadIdx.x;
    const int lane = tid & 31;
    const int warp = tid >> 5;
    const int rowb = blockIdx.x * ROWS;

    // ---- zero both A buffers, load wout/bout ----
    for (int i = tid * 16; i < SB; i += NTHR * 16) *(uint4*)(smem + i) = make_uint4(0, 0, 0, 0);
    for (int i = tid; i < 512; i += NTHR) { int k = i >> 3, o = i & 7; wo[i] = Wout[o * 64 + k]; }
    if (tid < 8) bo[tid] = bout[tid];
    __syncthreads();
    if (tid < ROWS) {
        ((half*)(smem + SA))[tid * KP + 72]        = __float2half(1.0f);
        ((half*)(smem + SA + ABUF))[tid * KP + 72] = __float2half(1.0f);
        const float4* p = (const float4*)(x + ((size_t)rowb + tid) * 8);
        float4 a = p[0], b = p[1];
        float v[8] = {a.x, a.y, a.z, a.w, b.x, b.y, b.z, b.w};
        stage_x((half*)(smem + SA), (half*)(smem + SA + ALO), tid, v);
    }
    __syncthreads();

    // ---- encoder B ----
    u32 Bh[4][KC][2];
    const u32 fb = sptr(Bs) + (u32)((lane & 7) * RB + ((lane >> 3) & 1) * 16);
    u32 blq[4];
    #pragma unroll
    for (int q = 0; q < 4; q++) blq[q] = fb + (u32)((warp + 8 * q) * 8 * RB);

    build_B(Bs, eWih, eWhh, ebih, ebhh, Wout, bout, 0, 0, tid);  __syncthreads();
    load_frags(fb, warp, Bh);                                    __syncthreads();
    build_B(Bs, eWih, eWhh, ebih, ebhh, Wout, bout, 0, 1, tid);  __syncthreads();

    u32 aoff0, aoff1;
    {
        int t8 = lane >> 3, lr = lane & 7;
        aoff0 = (u32)((0 * 16 + (t8 & 1) * 8 + lr) * RB + (t8 >> 1) * 16);
        aoff1 = (u32)((1 * 16 + (t8 & 1) * 8 + lr) * RB + (t8 >> 1) * 16);
    }
    const u32 sbA = sptr(smem + SA);

    float D[2][4][4];
    float hold[2][4];
    #pragma unroll
    for (int mt = 0; mt < 2; mt++)
        #pragma unroll
        for (int j = 0; j < 4; j++) hold[mt][j] = 0.0f;

    int b = 0;

    // ---- anti-phase stagger: wave-2 CTAs do one dummy GEMM (results discarded) ----
    if (blockIdx.x >= 148) {
        float Dd[2][4][4];
        gemm_step<false>(sbA + aoff0, sbA + aoff1, blq, Bh, Dd);
    }

    // =========================== ENCODER (1 sync/step) ===========================
    for (int t = 0; t < SEQ; t++) {
        float xv[8];
        const bool pf = (tid < ROWS) && (t + 1 < SEQ);
        if (pf) {
            const float4* p = (const float4*)(x + ((size_t)(t + 1) * BATCH + rowb + tid) * 8);
            float4 a = p[0], c = p[1];
            xv[0]=a.x; xv[1]=a.y; xv[2]=a.z; xv[3]=a.w; xv[4]=c.x; xv[5]=c.y; xv[6]=c.z; xv[7]=c.w;
        }
        u32 ab = sbA + (u32)(b * ABUF);
        gemm_step<false>(ab + aoff0, ab + aoff1, blq, Bh, D);
        int nb = b ^ 1;
        half* AhiN = (half*)(smem + SA + nb * ABUF);
        half* AloN = AhiN + ALO / 2;
        epi(AhiN, AloN, warp, lane, D, hold);
        if (pf) stage_x(AhiN, AloN, tid, xv);
        __syncthreads();
        b = nb;
    }

    // ---- decoder step 0 (unfolded, x = xy[0]) ----
    build_B(Bs, dWih, dWhh, dbih, dbhh, Wout, bout, 0, 0, tid);  __syncthreads();
    load_frags(fb, warp, Bh);                                    __syncthreads();
    build_B(Bs, dWih, dWhh, dbih, dbhh, Wout, bout, 0, 1, tid);
    if (tid < ROWS) {
        const float4* p = (const float4*)(xy + ((size_t)rowb + tid) * 8);
        float4 a = p[0], c = p[1];
        float v[8] = {a.x, a.y, a.z, a.w, c.x, c.y, c.z, c.w};
        half* Ahi = (half*)(smem + SA + b * ABUF);
        stage_x(Ahi, Ahi + ALO / 2, tid, v);
    }
    __syncthreads();

    {
        u32 ab = sbA + (u32)(b * ABUF);
        gemm_step<false>(ab + aoff0, ab + aoff1, blq, Bh, D);
        int nb = b ^ 1;
        half* AhiN = (half*)(smem + SA + nb * ABUF);
        half* AloN = AhiN + ALO / 2;
        epi(AhiN, AloN, warp, lane, D, hold);     // h_1 -> buf nb
        __syncthreads();
        b = nb;
    }

    // ---- fold Wout into decoder weights (steps >= 1) ----
    build_B(Bs, dWih, dWhh, dbih, dbhh, Wout, bout, 1, 0, tid);  __syncthreads();
    load_frags(fb, warp, Bh);                                    __syncthreads();
    build_B(Bs, dWih, dWhh, dbih, dbhh, Wout, bout, 1, 1, tid);  __syncthreads();

    const int orr = tid >> 3, oo = tid & 7;       // 32 rows x 8 outs = 256 threads
    const float bop = bo[oo];

    // =========================== DECODER (folded, 1 sync/step) ===========================
    for (int t = 1; t < LAB; t++) {
        u32 ab = sbA + (u32)(b * ABUF);
        half* Ahi = (half*)(smem + SA + b * ABUF);
        half* Alo = Ahi + ALO / 2;
        gemm_step<true>(ab + aoff0, ab + aoff1, blq, Bh, D);
        // out(t-1) = h_t @ Wout^T + bout ; h_t is the buffer gemm just read (stable)
        out[((size_t)(t - 1) * BATCH + rowb + orr) * 8 + oo] = oproj(Ahi, Alo, wo, bop, orr, oo);
        int nb = b ^ 1;
        half* AhiN = (half*)(smem + SA + nb * ABUF);
        half* AloN = AhiN + ALO / 2;
        epi(AhiN, AloN, warp, lane, D, hold);
        __syncthreads();
        b = nb;
    }
    // final out(127) from h_128 (current buffer b)
    {
        half* Ahi = (half*)(smem + SA + b * ABUF);
        half* Alo = Ahi + ALO / 2;
        out[((size_t)(LAB - 1) * BATCH + rowb + orr) * 8 + oo] = oproj(Ahi, Alo, wo, bop, orr, oo);
    }
}

extern "C" void kernel_launch(void* const* d_in, const int* in_sizes, int n_in,
                              void* d_out, int out_size) {
    (void)in_sizes; (void)n_in; (void)out_size;
    cudaFuncSetAttribute(seq2seq_mma_kernel,
                         cudaFuncAttributeMaxDynamicSharedMemorySize, STOT);
    seq2seq_mma_kernel<<<NBLK, NTHR, STOT>>>(
        (const float*)d_in[0], (const float*)d_in[1],
        (const float*)d_in[2], (const float*)d_in[3],
        (const float*)d_in[4], (const float*)d_in[5],
        (const float*)d_in[6], (const float*)d_in[7],
        (const float*)d_in[8], (const float*)d_in[9],
        (const float*)d_in[10], (const float*)d_in[11],
        (float*)d_out);
}

// round 14
// speedup vs baseline: 1.2003x; 1.0040x over previous
#include <cuda_runtime.h>
#include <cuda_fp16.h>

typedef unsigned int u32;

#define SEQ   256
#define LAB   128
#define BATCH 8192
#define ROWS  32
#define NBLK  (BATCH / ROWS)   // 256
#define NTHR  256
#define KP    88
#define RB    176
#define KC    5                // K=80: 64 h + 8 x + 1 bias + pad

// ---- SMEM byte offsets ----
// A: [2 buf][hi|lo][32][88] fp16.  buf stride 11264, hi->lo +5632
#define SA    0
#define ABUF  11264
#define ALO   5632
#define SB    22528            // B scratch; B_lo stays resident
#define SWOUT 67584            // [64][8] f32
#define SBOUT 69632            // [8] f32
#define STOT  69696

static __device__ __forceinline__ u32 sptr(const void* p) {
    return (u32)__cvta_generic_to_shared(p);
}
static __device__ __forceinline__ void ldm4(u32* r, u32 a) {
    asm volatile("ldmatrix.sync.aligned.m8n8.x4.shared.b16 {%0,%1,%2,%3},[%4];"
        : "=r"(r[0]), "=r"(r[1]), "=r"(r[2]), "=r"(r[3]) : "r"(a));
}
static __device__ __forceinline__ void ldm2(u32* r, u32 a) {
    asm volatile("ldmatrix.sync.aligned.m8n8.x2.shared.b16 {%0,%1},[%2];"
        : "=r"(r[0]), "=r"(r[1]) : "r"(a));
}
static __device__ __forceinline__ void mmaop(float* d, const u32* a, const u32* b) {
    asm volatile("mma.sync.aligned.m16n8k16.row.col.f32.f16.f16.f32 "
        "{%0,%1,%2,%3},{%4,%5,%6,%7},{%8,%9},{%0,%1,%2,%3};"
        : "+f"(d[0]), "+f"(d[1]), "+f"(d[2]), "+f"(d[3])
        : "r"(a[0]), "r"(a[1]), "r"(a[2]), "r"(a[3]), "r"(b[0]), "r"(b[1]));
}
static __device__ __forceinline__ float tanha(float x) {
    float y; asm("tanh.approx.f32 %0,%1;" : "=f"(y) : "f"(x)); return y;
}
static __device__ __forceinline__ float sigt(float x) { return fmaf(0.5f, tanha(0.5f * x), 0.5f); }

// B[n][k]: r 0-63, z 64-127, ni 128-191, nh 192-255.
// fold=0: k<64 Whh (ni zero), k64-71 Wih, k72 bias.
// fold=1: k<64 Whh + Wih@Wout (ni: Wih@Wout), k64-71 zero, k72 bias + Wih@bout.
static __device__ void build_B(half* Bs,
                               const float* __restrict__ Wih, const float* __restrict__ Whh,
                               const float* __restrict__ bih, const float* __restrict__ bhh,
                               const float* __restrict__ Wout, const float* __restrict__ bout,
                               int fold, int term, int tid) {
    for (int i = tid; i < 256 * KP; i += NTHR) {
        int n = i / KP, k = i % KP;
        float v = 0.0f;
        if (k < 64) {
            if (n < 128) v = Whh[n * 64 + k];
            else if (n >= 192) v = Whh[(n - 64) * 64 + k];
            if (fold && n < 192) {
                #pragma unroll
                for (int o = 0; o < 8; o++) v = fmaf(Wih[n * 8 + o], Wout[o * 64 + k], v);
            }
        } else if (k < 72) {
            if (!fold && n < 192) v = Wih[n * 8 + (k - 64)];
        } else if (k == 72) {
            v = (n < 128) ? bih[n] + bhh[n] : (n < 192 ? bih[n] : bhh[n - 64]);
            if (fold && n < 192) {
                #pragma unroll
                for (int o = 0; o < 8; o++) v = fmaf(Wih[n * 8 + o], bout[o], v);
            }
        }
        half h = __float2half_rn(v);
        if (term) h = __float2half_rn(v - __half2float(h));
        Bs[i] = h;
    }
}

static __device__ __forceinline__ void load_frags(u32 fb, int warp, u32 (&Bh)[4][KC][2]) {
    #pragma unroll
    for (int q = 0; q < 4; q++) {
        u32 bq = fb + (u32)((warp + 8 * q) * 8 * RB);
        #pragma unroll
        for (int kc = 0; kc < KC; kc++) ldm2(Bh[q][kc], bq + kc * 32);
    }
}

// Two m-tile GEMM. NIF: ni full-K (folded decoder); else ni only kc=4.
template<bool NIF>
static __device__ __forceinline__ void gemm_step(u32 aHi0, u32 aHi1, const u32 blq[4],
                                                 const u32 (&Bh)[4][KC][2], float (&D)[2][4][4]) {
    #pragma unroll
    for (int mt = 0; mt < 2; mt++)
        #pragma unroll
        for (int q = 0; q < 4; q++)
            #pragma unroll
            for (int e = 0; e < 4; e++) D[mt][q][e] = 0.0f;
    #pragma unroll
    for (int kc = 0; kc < KC; kc++) {
        u32 ah[2][4], al[2][4];
        ldm4(ah[0], aHi0 + kc * 32);
        ldm4(ah[1], aHi1 + kc * 32);
        ldm4(al[0], aHi0 + ALO + kc * 32);
        ldm4(al[1], aHi1 + ALO + kc * 32);
        u32 b0[2], b1[2], b3[2];
        ldm2(b0, blq[0] + kc * 32);
        ldm2(b1, blq[1] + kc * 32);
        ldm2(b3, blq[3] + kc * 32);
        #pragma unroll
        for (int mt = 0; mt < 2; mt++) {
            mmaop(D[mt][0], ah[mt], Bh[0][kc]); mmaop(D[mt][0], al[mt], Bh[0][kc]); mmaop(D[mt][0], ah[mt], b0);
            mmaop(D[mt][1], ah[mt], Bh[1][kc]); mmaop(D[mt][1], al[mt], Bh[1][kc]); mmaop(D[mt][1], ah[mt], b1);
            mmaop(D[mt][3], ah[mt], Bh[3][kc]); mmaop(D[mt][3], al[mt], Bh[3][kc]); mmaop(D[mt][3], ah[mt], b3);
        }
        if (NIF || kc == KC - 1) {
            u32 b2[2]; ldm2(b2, blq[2] + kc * 32);
            #pragma unroll
            for (int mt = 0; mt < 2; mt++) {
                mmaop(D[mt][2], ah[mt], Bh[2][kc]); mmaop(D[mt][2], al[mt], Bh[2][kc]); mmaop(D[mt][2], ah[mt], b2);
            }
        }
    }
}

// Gates in regs; write h' (hi/lo) into next A buffer.
static __device__ __forceinline__ void epi(half* AhiN, half* AloN, int warp, int lane,
                                           float (&D)[2][4][4], float (&hold)[2][4]) {
    const int r0 = lane >> 2;
    const int c0 = warp * 8 + 2 * (lane & 3);
    #pragma unroll
    for (int mt = 0; mt < 2; mt++) {
        float h[4];
        #pragma unroll
        for (int j = 0; j < 4; j++) {
            float R = sigt(D[mt][0][j]);
            float Z = sigt(D[mt][1][j]);
            float N = tanha(fmaf(R, D[mt][3][j], D[mt][2][j]));
            h[j] = fmaf(Z, hold[mt][j] - N, N);
            hold[mt][j] = h[j];
        }
        int ra = mt * 16 + r0, rb = ra + 8;
        half2 h2a = __floats2half2_rn(h[0], h[1]);
        half2 l2a = __floats2half2_rn(h[0] - __low2float(h2a), h[1] - __high2float(h2a));
        half2 h2b = __floats2half2_rn(h[2], h[3]);
        half2 l2b = __floats2half2_rn(h[2] - __low2float(h2b), h[3] - __high2float(h2b));
        *(half2*)(AhiN + ra * KP + c0) = h2a;
        *(half2*)(AloN + ra * KP + c0) = l2a;
        *(half2*)(AhiN + rb * KP + c0) = h2b;
        *(half2*)(AloN + rb * KP + c0) = l2b;
    }
}

static __device__ __forceinline__ void stage_x(half* Ahi, half* Alo, int row, const float* v) {
    #pragma unroll
    for (int j = 0; j < 4; j++) {
        float a = v[2 * j], b = v[2 * j + 1];
        half2 h2 = __floats2half2_rn(a, b);
        half2 l2 = __floats2half2_rn(a - __low2float(h2), b - __high2float(h2));
        *(half2*)(Ahi + row * KP + 64 + 2 * j) = h2;
        *(half2*)(Alo + row * KP + 64 + 2 * j) = l2;
    }
}

// Out-projection: one scalar out for (row r, output oo), reading h from buffer.
static __device__ __forceinline__ float oproj(const half* Ahi, const half* Alo,
                                              const float* wo, float acc, int r, int oo) {
    const half2* rh = (const half2*)(Ahi + r * KP);
    const half2* rl = (const half2*)(Alo + r * KP);
    #pragma unroll 8
    for (int k2 = 0; k2 < 32; k2++) {
        float2 hq = __half22float2(rh[k2]);
        float2 lq = __half22float2(rl[k2]);
        acc = fmaf(hq.x + lq.x, wo[(2 * k2) * 8 + oo],
              fmaf(hq.y + lq.y, wo[(2 * k2 + 1) * 8 + oo], acc));
    }
    return acc;
}

__global__ __launch_bounds__(NTHR, 2)
void seq2seq_mma_kernel(const float* __restrict__ x,
                        const float* __restrict__ xy,
                        const float* __restrict__ eWih, const float* __restrict__ eWhh,
                        const float* __restrict__ ebih, const float* __restrict__ ebhh,
                        const float* __restrict__ dWih, const float* __restrict__ dWhh,
                        const float* __restrict__ dbih, const float* __restrict__ dbhh,
                        const float* __restrict__ Wout, const float* __restrict__ bout,
                        float* __restrict__ out)
{
    extern __shared__ char smem[];
    half*  Bs = (half*)(smem + SB);
    float* wo = (float*)(smem + SWOUT);
    float* bo = (float*)(smem + SBOUT);

    const int tid  = threadIdx.x;
    const int lane = tid & 31;
    const int warp = tid >> 5;
    const int rowb = blockIdx.x * ROWS;

    // ---- zero both A buffers, load wout/bout ----
    for (int i = tid * 16; i < SB; i += NTHR * 16) *(uint4*)(smem + i) = make_uint4(0, 0, 0, 0);
    for (int i = tid; i < 512; i += NTHR) { int k = i >> 3, o = i & 7; wo[i] = Wout[o * 64 + k]; }
    if (tid < 8) bo[tid] = bout[tid];
    __syncthreads();
    if (tid < ROWS) {
        ((half*)(smem + SA))[tid * KP + 72]        = __float2half(1.0f);
        ((half*)(smem + SA + ABUF))[tid * KP + 72] = __float2half(1.0f);
        const float4* p = (const float4*)(x + ((size_t)rowb + tid) * 8);
        float4 a = p[0], b = p[1];
        float v[8] = {a.x, a.y, a.z, a.w, b.x, b.y, b.z, b.w};
        stage_x((half*)(smem + SA), (half*)(smem + SA + ALO), tid, v);
    }
    __syncthreads();

    // ---- encoder B ----
    u32 Bh[4][KC][2];
    const u32 fb = sptr(Bs) + (u32)((lane & 7) * RB + ((lane >> 3) & 1) * 16);
    u32 blq[4];
    #pragma unroll
    for (int q = 0; q < 4; q++) blq[q] = fb + (u32)((warp + 8 * q) * 8 * RB);

    build_B(Bs, eWih, eWhh, ebih, ebhh, Wout, bout, 0, 0, tid);  __syncthreads();
    load_frags(fb, warp, Bh);                                    __syncthreads();
    build_B(Bs, eWih, eWhh, ebih, ebhh, Wout, bout, 0, 1, tid);  __syncthreads();

    u32 aoff0, aoff1;
    {
        int t8 = lane >> 3, lr = lane & 7;
        aoff0 = (u32)((0 * 16 + (t8 & 1) * 8 + lr) * RB + (t8 >> 1) * 16);
        aoff1 = (u32)((1 * 16 + (t8 & 1) * 8 + lr) * RB + (t8 >> 1) * 16);
    }
    const u32 sbA = sptr(smem + SA);

    float D[2][4][4];
    float hold[2][4];
    #pragma unroll
    for (int mt = 0; mt < 2; mt++)
        #pragma unroll
        for (int j = 0; j < 4; j++) hold[mt][j] = 0.0f;

    int b = 0;

    // =========================== ENCODER (1 sync/step) ===========================
    for (int t = 0; t < SEQ; t++) {
        float xv[8];
        const bool pf = (tid < ROWS) && (t + 1 < SEQ);
        if (pf) {
            const float4* p = (const float4*)(x + ((size_t)(t + 1) * BATCH + rowb + tid) * 8);
            float4 a = p[0], c = p[1];
            xv[0]=a.x; xv[1]=a.y; xv[2]=a.z; xv[3]=a.w; xv[4]=c.x; xv[5]=c.y; xv[6]=c.z; xv[7]=c.w;
        }
        u32 ab = sbA + (u32)(b * ABUF);
        gemm_step<false>(ab + aoff0, ab + aoff1, blq, Bh, D);
        int nb = b ^ 1;
        half* AhiN = (half*)(smem + SA + nb * ABUF);
        half* AloN = AhiN + ALO / 2;
        epi(AhiN, AloN, warp, lane, D, hold);
        if (pf) stage_x(AhiN, AloN, tid, xv);
        __syncthreads();
        b = nb;
    }

    // ---- decoder step 0 (unfolded, x = xy[0]) ----
    build_B(Bs, dWih, dWhh, dbih, dbhh, Wout, bout, 0, 0, tid);  __syncthreads();
    load_frags(fb, warp, Bh);                                    __syncthreads();
    build_B(Bs, dWih, dWhh, dbih, dbhh, Wout, bout, 0, 1, tid);
    if (tid < ROWS) {
        const float4* p = (const float4*)(xy + ((size_t)rowb + tid) * 8);
        float4 a = p[0], c = p[1];
        float v[8] = {a.x, a.y, a.z, a.w, c.x, c.y, c.z, c.w};
        half* Ahi = (half*)(smem + SA + b * ABUF);
        stage_x(Ahi, Ahi + ALO / 2, tid, v);
    }
    __syncthreads();

    {
        u32 ab = sbA + (u32)(b * ABUF);
        gemm_step<false>(ab + aoff0, ab + aoff1, blq, Bh, D);
        int nb = b ^ 1;
        half* AhiN = (half*)(smem + SA + nb * ABUF);
        half* AloN = AhiN + ALO / 2;
        epi(AhiN, AloN, warp, lane, D, hold);     // h_1 -> buf nb
        __syncthreads();
        b = nb;
    }

    // ---- fold Wout into decoder weights (steps >= 1) ----
    build_B(Bs, dWih, dWhh, dbih, dbhh, Wout, bout, 1, 0, tid);  __syncthreads();
    load_frags(fb, warp, Bh);                                    __syncthreads();
    build_B(Bs, dWih, dWhh, dbih, dbhh, Wout, bout, 1, 1, tid);  __syncthreads();

    const int orr = tid >> 3, oo = tid & 7;       // 32 rows x 8 outs = 256 threads
    const float bop = bo[oo];

    // =========================== DECODER (folded, 1 sync/step) ===========================
    for (int t = 1; t < LAB; t++) {
        u32 ab = sbA + (u32)(b * ABUF);
        half* Ahi = (half*)(smem + SA + b * ABUF);
        half* Alo = Ahi + ALO / 2;
        gemm_step<true>(ab + aoff0, ab + aoff1, blq, Bh, D);
        // out(t-1) = h_t @ Wout^T + bout ; h_t is the buffer gemm just read (stable)
        out[((size_t)(t - 1) * BATCH + rowb + orr) * 8 + oo] = oproj(Ahi, Alo, wo, bop, orr, oo);
        int nb = b ^ 1;
        half* AhiN = (half*)(smem + SA + nb * ABUF);
        half* AloN = AhiN + ALO / 2;
        epi(AhiN, AloN, warp, lane, D, hold);
        __syncthreads();
        b = nb;
    }
    // final out(127) from h_128 (current buffer b)
    {
        half* Ahi = (half*)(smem + SA + b * ABUF);
        half* Alo = Ahi + ALO / 2;
        out[((size_t)(LAB - 1) * BATCH + rowb + orr) * 8 + oo] = oproj(Ahi, Alo, wo, bop, orr, oo);
    }
}

extern "C" void kernel_launch(void* const* d_in, const int* in_sizes, int n_in,
                              void* d_out, int out_size) {
    (void)in_sizes; (void)n_in; (void)out_size;
    cudaFuncSetAttribute(seq2seq_mma_kernel,
                         cudaFuncAttributeMaxDynamicSharedMemorySize, STOT);
    seq2seq_mma_kernel<<<NBLK, NTHR, STOT>>>(
        (const float*)d_in[0], (const float*)d_in[1],
        (const float*)d_in[2], (const float*)d_in[3],
        (const float*)d_in[4], (const float*)d_in[5],
        (const float*)d_in[6], (const float*)d_in[7],
        (const float*)d_in[8], (const float*)d_in[9],
        (const float*)d_in[10], (const float*)d_in[11],
        (float*)d_out);
}